// round 14
// baseline (speedup 1.0000x reference)
#include <cuda_runtime.h>
#include <cuda_bf16.h>
#include <cuda_fp16.h>
#include <cstdint>

// ---------------- problem constants ----------------
#define M_ROWS   4096
#define K_DIM    784
#define K_PAD    832           // 13 * 64
#define N_BASAL  16384
#define NUM_CLS  10
#define NUM_ACT  492
#define ZK       1.8806f       // Phi^-1(1 - 492/16384)
#define WSIG     0.10f         // window half-width in sigma units (5.1 SE)
#define AERR     0.035f        // bf16 GEMM err (0.03) + fp16 pack err (0.005)
#define BW       0.08f         // rescore band half-width
#define EMIT_SLACK 0.01f
#define MAXC_G   1024
#define MAXBAND  256
#define PBINS    256
#define ESLOTS   40

// ---------------- GEMM tiling: BK=64, swizzled 128B rows ----------------
#define BM 128
#define BN 128
#define BK 64
#define NCHUNK (K_PAD / BK)    // 13
#define NSTAGE 3
#define ROW_BYTES 128          // swizzle instead of skew
#define A_STAGE_BYTES (BM * ROW_BYTES)   // 16384
#define B_STAGE_BYTES (BN * ROW_BYTES)   // 16384
#define STAGE_BYTES (A_STAGE_BYTES + B_STAGE_BYTES)   // 32768
#define SMEM_TOTAL (NSTAGE * STAGE_BYTES)   // 98304 -> 2 CTAs/SM

// ---------------- scratch ----------------
__device__ unsigned int   g_mask[N_BASAL];
__device__ __nv_bfloat16  g_A[(size_t)M_ROWS * K_PAD];
__device__ __nv_bfloat16  g_B[(size_t)N_BASAL * K_PAD];
__device__ float          g_Bt[(size_t)N_BASAL * K_DIM];
__device__ float          g_sigma[M_ROWS];
__device__ int            g_ccnt[M_ROWS];
__device__ unsigned int   g_cand[(size_t)M_ROWS * MAXC_G];   // 16 MB

// ---------------- asm helpers ----------------
__device__ __forceinline__ uint32_t smem_u32(const void* p) {
    uint32_t a;
    asm("{ .reg .u64 t; cvta.to.shared.u64 t, %1; cvt.u32.u64 %0, t; }" : "=r"(a) : "l"(p));
    return a;
}
__device__ __forceinline__ void cp_async16(uint32_t dst, const void* src) {
    asm volatile("cp.async.cg.shared.global [%0], [%1], 16;" :: "r"(dst), "l"(src) : "memory");
}
__device__ __forceinline__ void cp_commit() {
    asm volatile("cp.async.commit_group;" ::: "memory");
}
template <int N>
__device__ __forceinline__ void cp_wait() {
    asm volatile("cp.async.wait_group %0;" :: "n"(N) : "memory");
}
__device__ __forceinline__ void ldm_x4(uint32_t* r, uint32_t addr) {
    asm volatile("ldmatrix.sync.aligned.m8n8.x4.shared.b16 {%0,%1,%2,%3}, [%4];"
                 : "=r"(r[0]), "=r"(r[1]), "=r"(r[2]), "=r"(r[3]) : "r"(addr));
}
__device__ __forceinline__ void mma_bf16(float* c, const uint32_t* a, uint32_t b0, uint32_t b1) {
    asm volatile("mma.sync.aligned.m16n8k16.row.col.f32.bf16.bf16.f32 "
                 "{%0,%1,%2,%3}, {%4,%5,%6,%7}, {%8,%9}, {%0,%1,%2,%3};"
                 : "+f"(c[0]), "+f"(c[1]), "+f"(c[2]), "+f"(c[3])
                 : "r"(a[0]), "r"(a[1]), "r"(a[2]), "r"(a[3]), "r"(b0), "r"(b1));
}

// ---------------------------------------------------------------------------
__global__ void init_kernel() {
    int i = blockIdx.x * 256 + threadIdx.x;
    if (i < M_ROWS) g_ccnt[i] = 0;
}

__global__ void pack_syn_kernel(const float* __restrict__ syn) {
    int j = blockIdx.x * blockDim.x + threadIdx.x;
    if (j < N_BASAL) {
        unsigned int m = 0;
#pragma unroll
        for (int c = 0; c < NUM_CLS; ++c)
            m |= (syn[c * N_BASAL + j] > 0.5f) ? (1u << c) : 0u;
        g_mask[j] = m;
    }
}

// ---------------------------------------------------------------------------
// A: bf16(image) + per-row sigma = 0.1*||x||
// ---------------------------------------------------------------------------
__global__ __launch_bounds__(256)
void conv_a_kernel(const float* __restrict__ img) {
    __shared__ float wsum[8];
    const int m = blockIdx.x;
    const int tid = threadIdx.x;
    const float* src = img + (size_t)m * K_DIM;
    __nv_bfloat16* dst = g_A + (size_t)m * K_PAD;
    float ss = 0.0f;
    for (int k = tid; k < K_PAD; k += 256) {
        float v = (k < K_DIM) ? src[k] : 0.0f;
        dst[k] = __float2bfloat16(v);
        ss = fmaf(v, v, ss);
    }
#pragma unroll
    for (int o = 16; o > 0; o >>= 1) ss += __shfl_xor_sync(0xFFFFFFFFu, ss, o);
    if ((tid & 31) == 0) wsum[tid >> 5] = ss;
    __syncthreads();
    if (tid == 0) {
        float t = 0.0f;
#pragma unroll
        for (int w = 0; w < 8; ++w) t += wsum[w];
        g_sigma[m] = 0.1f * sqrtf(t);
    }
}

// ---------------------------------------------------------------------------
// B: transpose proj -> bf16 g_B [n][K_PAD] and fp32 g_Bt [n][K_DIM]
// ---------------------------------------------------------------------------
__global__ void conv_b_kernel(const float* __restrict__ proj) {
    __shared__ float t[32][33];
    int k0 = blockIdx.x * 32, n0 = blockIdx.y * 32;
    int tx = threadIdx.x, ty = threadIdx.y;   // 32 x 8
#pragma unroll
    for (int i = 0; i < 32; i += 8) {
        int kk = k0 + ty + i;
        t[ty + i][tx] = (kk < K_DIM) ? proj[(size_t)kk * N_BASAL + n0 + tx] : 0.0f;
    }
    __syncthreads();
#pragma unroll
    for (int i = 0; i < 32; i += 8) {
        int n = n0 + ty + i;
        int k = k0 + tx;
        if (k < K_PAD) {
            float v = t[tx][ty + i];
            g_B[(size_t)n * K_PAD + k] = __float2bfloat16(v);
            if (k < K_DIM) g_Bt[(size_t)n * K_DIM + k] = v;
        }
    }
}

// ---------------------------------------------------------------------------
// GEMM: BK=64, XOR-swizzled 128B rows, NSTAGE=3, fused smem-staged emit.
// ---------------------------------------------------------------------------
__global__ __launch_bounds__(256, 2)
void gemm_mma_kernel() {
    extern __shared__ char smem[];
    const uint32_t sb = smem_u32(smem);
    const int tid = threadIdx.x;
    const int lane = tid & 31;
    const int wid = tid >> 5;
    const int warpM = wid >> 2;          // 0..1
    const int warpN = wid & 3;           // 0..3
    const int m0 = blockIdx.y * BM;
    const int n0 = blockIdx.x * BN;

    const char* Abase = (const char*)g_A + (size_t)m0 * (K_PAD * 2);
    const char* Bbase = (const char*)g_B + (size_t)n0 * (K_PAD * 2);

    // loader: lr = row 0..127, two 4-chunk groups per row
    const int lr  = tid >> 1;
    const int lc4 = (tid & 1) * 4;
    const int lsw = lr & 7;              // store swizzle for this row

    auto load_stage = [&](int c, int s) {
        const uint32_t st = sb + s * STAGE_BYTES;
        const size_t koff = (size_t)c * (BK * 2);
        const char* Arow = Abase + (size_t)lr * (K_PAD * 2) + koff;
        const char* Brow = Bbase + (size_t)lr * (K_PAD * 2) + koff;
        const uint32_t Adst = st + lr * ROW_BYTES;
        const uint32_t Bdst = st + A_STAGE_BYTES + lr * ROW_BYTES;
#pragma unroll
        for (int i = 0; i < 4; ++i) {
            const int cc = lc4 + i;
            const uint32_t sw = (uint32_t)((cc ^ lsw) << 4);
            cp_async16(Adst + sw, Arow + cc * 16);
            cp_async16(Bdst + sw, Brow + cc * 16);
        }
        cp_commit();
    };

    float acc[4][4][4];
#pragma unroll
    for (int i = 0; i < 4; ++i)
#pragma unroll
        for (int j = 0; j < 4; ++j)
#pragma unroll
            for (int q = 0; q < 4; ++q) acc[i][j][q] = 0.0f;

    // ldmatrix addressing: lanes 0-15 rows at first 16B of kstep, 16-31 second
    const int lrow = lane & 15;
    const int half = lane >> 4;          // 0/1
    const int swl = lrow & 7;            // read swizzle per lane

    uint32_t aRowB[4], bRowB[2];
#pragma unroll
    for (int mt = 0; mt < 4; ++mt)
        aRowB[mt] = (uint32_t)((warpM * 64 + mt * 16 + lrow) * ROW_BYTES);
#pragma unroll
    for (int nt = 0; nt < 2; ++nt)
        bRowB[nt] = (uint32_t)((warpN * 32 + nt * 16 + lrow) * ROW_BYTES) + A_STAGE_BYTES;

    load_stage(0, 0);
    load_stage(1, 1);

    for (int c = 0; c < NCHUNK; ++c) {
        const int s = c % NSTAGE;
        cp_wait<1>();
        __syncthreads();
        if (c + 2 < NCHUNK) load_stage(c + 2, (c + 2) % NSTAGE);
        else cp_commit();   // empty group keeps wait accounting safe

        const uint32_t st = sb + s * STAGE_BYTES;
#pragma unroll
        for (int ks = 0; ks < 4; ++ks) {
            const uint32_t sw = (uint32_t)((((ks << 1) + half) ^ swl) << 4);
            uint32_t af[4][4];
#pragma unroll
            for (int mt = 0; mt < 4; ++mt)
                ldm_x4(af[mt], st + aRowB[mt] + sw);
            uint32_t bf[2][4];
#pragma unroll
            for (int nt = 0; nt < 2; ++nt)
                ldm_x4(bf[nt], st + bRowB[nt] + sw);
#pragma unroll
            for (int mt = 0; mt < 4; ++mt) {
#pragma unroll
                for (int n8 = 0; n8 < 4; ++n8) {
                    const int nt = n8 >> 1, hi = n8 & 1;
                    mma_bf16(acc[mt][n8], af[mt], bf[nt][hi], bf[nt][hi + 2]);
                }
            }
        }
    }

    // -------- smem-staged emit epilogue --------
    __syncthreads();
    float*        s_lo   = (float*)smem;                      // 512 B
    int*          s_scnt = (int*)(smem + 512);                // 512 B
    unsigned int* s_buf  = (unsigned int*)(smem + 1024);      // 20 KB

    if (tid < BM) {
        const float sg = g_sigma[m0 + tid];
        s_lo[tid] = ZK * sg - (WSIG * sg + AERR) - EMIT_SLACK;
        s_scnt[tid] = 0;
    }
    __syncthreads();

    const int grp = lane >> 2;
    const int tj  = lane & 3;
    float lo8[4][2];
#pragma unroll
    for (int mt = 0; mt < 4; ++mt)
#pragma unroll
        for (int h = 0; h < 2; ++h)
            lo8[mt][h] = s_lo[warpM * 64 + mt * 16 + grp + h * 8];

#pragma unroll
    for (int mt = 0; mt < 4; ++mt) {
#pragma unroll
        for (int n8 = 0; n8 < 4; ++n8) {
#pragma unroll
            for (int q = 0; q < 4; ++q) {
                const int h = q >> 1;
                const float v = acc[mt][n8][q];
                if (v >= lo8[mt][h]) {
                    const int lr2 = warpM * 64 + mt * 16 + grp + h * 8;
                    const int col = n0 + warpN * 32 + n8 * 8 + tj * 2 + (q & 1);
                    unsigned int pk =
                        ((unsigned int)__half_as_ushort(__float2half_rn(v)) << 16) |
                        (unsigned int)col;
                    int p = atomicAdd(&s_scnt[lr2], 1);
                    if (p < ESLOTS) {
                        s_buf[lr2 * ESLOTS + p] = pk;
                    } else {
                        const int row = m0 + lr2;
                        int qg = atomicAdd(&g_ccnt[row], 1);
                        if (qg < MAXC_G) g_cand[(size_t)row * MAXC_G + qg] = pk;
                    }
                }
            }
        }
    }
    __syncthreads();

    if (tid < BM) {
        int c = s_scnt[tid];
        if (c > ESLOTS) c = ESLOTS;
        if (c > 0) {
            const int row = m0 + tid;
            int base = atomicAdd(&g_ccnt[row], c);
            unsigned int* dst = g_cand + (size_t)row * MAXC_G;
            for (int i = 0; i < c; ++i) {
                int p = base + i;
                if (p < MAXC_G) dst[p] = s_buf[tid * ESLOTS + i];
            }
        }
    }
}

// ---------------------------------------------------------------------------
// finalize (one block / row)
// ---------------------------------------------------------------------------
__global__ __launch_bounds__(256)
void finalize_kernel(const float* __restrict__ img, float* __restrict__ out) {
    const int row = blockIdx.x;
    const int tid = threadIdx.x;
    const int lane = tid & 31;
    const int wid = tid >> 5;

    __shared__ float cval[MAXC_G];
    __shared__ int   ccol[MAXC_G];
    __shared__ float4 s_img[K_DIM / 4];
    __shared__ unsigned int hist[PBINS];
    __shared__ int s_nsure, s_pb, s_nband, s_ntop;
    __shared__ int bidx[MAXBAND];
    __shared__ float bval[MAXBAND];
    __shared__ int ov[NUM_CLS];

    const int C = min(g_ccnt[row], MAXC_G);
    const float sig = g_sigma[row];
    const float tau = ZK * sig;
    const float w = WSIG * sig + AERR;
    const float lo = tau - w;
    const float hi = tau + w;
    const float binw = (hi - lo) / (float)PBINS;
    const float invbw = 1.0f / binw;

    const float4* img4 = (const float4*)(img + (size_t)row * K_DIM);
    for (int k = tid; k < K_DIM / 4; k += 256) s_img[k] = img4[k];
    for (int i = tid; i < PBINS; i += 256) hist[i] = 0;
    if (tid == 0) { s_nsure = 0; s_pb = -1; s_nband = 0; s_ntop = 0; }
    if (tid < NUM_CLS) ov[tid] = 0;

    const unsigned int* cp = g_cand + (size_t)row * MAXC_G;
    for (int i = tid; i < C; i += 256) {
        unsigned int p = cp[i];
        cval[i] = __half2float(__ushort_as_half((unsigned short)(p >> 16)));
        ccol[i] = (int)(p & 0xFFFFu);
    }
    __syncthreads();

    int cnt[NUM_CLS];
#pragma unroll
    for (int c = 0; c < NUM_CLS; ++c) cnt[c] = 0;

    int nsure = 0;
    for (int i = tid; i < C; i += 256) {
        const float v = cval[i];
        if (v > hi) {
            unsigned int m = g_mask[ccol[i]];
#pragma unroll
            for (int c = 0; c < NUM_CLS; ++c) cnt[c] += (m >> c) & 1u;
            ++nsure;
        } else {
            int b = (int)((v - lo) * invbw);
            b = min(max(b, 0), PBINS - 1);
            atomicAdd(&hist[b], 1u);
        }
    }
    atomicAdd(&s_nsure, nsure);
    __syncthreads();

    int k_remain = NUM_ACT - s_nsure;
    const int C_win = C - s_nsure;

    if (k_remain > 0 && k_remain >= C_win) {
        for (int i = tid; i < C; i += 256) {
            if (cval[i] <= hi) {
                unsigned int m = g_mask[ccol[i]];
#pragma unroll
                for (int c = 0; c < NUM_CLS; ++c) cnt[c] += (m >> c) & 1u;
            }
        }
    } else if (k_remain > 0) {
        if (wid == 0) {
            const unsigned int kk = (unsigned int)k_remain;
            unsigned int sum = 0;
            for (int i = 0; i < PBINS / 32; ++i)
                sum += hist[PBINS - 1 - lane * (PBINS / 32) - i];
            unsigned int pre = sum;
#pragma unroll
            for (int o = 1; o < 32; o <<= 1) {
                unsigned int t = __shfl_up_sync(0xFFFFFFFFu, pre, o);
                if (lane >= o) pre += t;
            }
            const unsigned int excl = pre - sum;
            if (excl < kk && pre >= kk) {
                unsigned int before = excl;
                for (int i = 0; i < PBINS / 32; ++i) {
                    int b = PBINS - 1 - lane * (PBINS / 32) - i;
                    unsigned int cc = hist[b];
                    if (before + cc >= kk) { s_pb = b; break; }
                    before += cc;
                }
            }
        }
        __syncthreads();

        const int pb = (s_pb >= 0) ? s_pb : 0;
        const float hi2 = lo + (float)(pb + 1) * binw + BW;
        const float lo2 = lo + (float)pb * binw - BW;

        int ntop = 0;
        for (int i = tid; i < C; i += 256) {
            const float v = cval[i];
            if (v > hi) continue;
            if (v > hi2) {
                unsigned int m = g_mask[ccol[i]];
#pragma unroll
                for (int c = 0; c < NUM_CLS; ++c) cnt[c] += (m >> c) & 1u;
                ++ntop;
            } else if (v >= lo2) {
                int p = atomicAdd(&s_nband, 1);
                if (p < MAXBAND) bidx[p] = ccol[i];
            }
        }
        atomicAdd(&s_ntop, ntop);
        __syncthreads();

        const int nband = min(s_nband, MAXBAND);
        for (int b = wid; b < nband; b += 8) {
            const float4* brow = (const float4*)(g_Bt + (size_t)bidx[b] * K_DIM);
            float s = 0.0f;
            for (int k = lane; k < K_DIM / 4; k += 32) {
                float4 bb = brow[k];
                float4 im = s_img[k];
                s = fmaf(im.x, bb.x, s);
                s = fmaf(im.y, bb.y, s);
                s = fmaf(im.z, bb.z, s);
                s = fmaf(im.w, bb.w, s);
            }
#pragma unroll
            for (int o = 16; o > 0; o >>= 1)
                s += __shfl_xor_sync(0xFFFFFFFFu, s, o);
            if (lane == 0) bval[b] = s;
        }
        __syncthreads();

        const int slots = k_remain - s_ntop;
        for (int b = tid; b < nband; b += 256) {
            const float vb = bval[b];
            const int ib = bidx[b];
            int r = 0;
            for (int d = 0; d < nband; ++d) {
                float vd = bval[d];
                r += (vd > vb || (vd == vb && bidx[d] < ib)) ? 1 : 0;
            }
            if (r < slots) {
                unsigned int m = g_mask[ib];
#pragma unroll
                for (int c = 0; c < NUM_CLS; ++c) cnt[c] += (m >> c) & 1u;
            }
        }
    }

#pragma unroll
    for (int c = 0; c < NUM_CLS; ++c)
        if (cnt[c]) atomicAdd(&ov[c], cnt[c]);
    __syncthreads();

    if (tid < NUM_CLS)
        out[row * NUM_CLS + tid] = (float)ov[tid];
}

// ---------------------------------------------------------------------------
// Launch
// ---------------------------------------------------------------------------
extern "C" void kernel_launch(void* const* d_in, const int* in_sizes, int n_in,
                              void* d_out, int out_size) {
    const float* image = (const float*)d_in[0];
    const float* proj  = (const float*)d_in[1];
    const float* syn   = (const float*)d_in[2];
    float* out = (float*)d_out;

    cudaFuncSetAttribute(gemm_mma_kernel, cudaFuncAttributeMaxDynamicSharedMemorySize, SMEM_TOTAL);

    init_kernel<<<(M_ROWS + 255) / 256, 256>>>();
    pack_syn_kernel<<<(N_BASAL + 255) / 256, 256>>>(syn);
    conv_a_kernel<<<M_ROWS, 256>>>(image);
    {
        dim3 grid((K_PAD + 31) / 32, N_BASAL / 32);   // 26 x 512
        conv_b_kernel<<<grid, dim3(32, 8)>>>(proj);
    }
    {
        dim3 grid(N_BASAL / BN, M_ROWS / BM);         // 128 x 32
        gemm_mma_kernel<<<grid, 256, SMEM_TOTAL>>>();
    }
    finalize_kernel<<<M_ROWS, 256>>>(image, out);
}

// round 15
// speedup vs baseline: 1.0241x; 1.0241x over previous
#include <cuda_runtime.h>
#include <cuda_bf16.h>
#include <cuda_fp16.h>
#include <cstdint>

// ---------------- problem constants ----------------
#define M_ROWS   4096
#define K_DIM    784
#define K_PAD    800           // 784 padded to 25*32
#define N_BASAL  16384
#define NUM_CLS  10
#define NUM_ACT  492
#define ZK       1.8806f       // Phi^-1(1 - 492/16384)
#define WSIG     0.10f         // window half-width in sigma units (5.1 SE)
#define AERR     0.035f        // bf16 GEMM err (0.03) + fp16 pack err (0.005)
#define BW       0.08f         // rescore band half-width
#define EMIT_SLACK 0.01f
#define MAXC_G   1024
#define MAXBAND  256
#define PBINS    256
#define ESLOTS   40

// ---------------- GEMM tiling (round-13 proven config) ----------------
#define BM 128
#define BN 128
#define BK 32
#define NCHUNK (K_PAD / BK)    // 25
#define NSTAGE 4
#define ROW_BYTES 80
#define A_STAGE_BYTES (BM * ROW_BYTES)
#define B_STAGE_BYTES (BN * ROW_BYTES)
#define STAGE_BYTES (A_STAGE_BYTES + B_STAGE_BYTES)
#define SMEM_TOTAL (NSTAGE * STAGE_BYTES)   // 81920

// ---------------- scratch ----------------
__device__ unsigned int   g_mask[N_BASAL];
__device__ __nv_bfloat16  g_A[(size_t)M_ROWS * K_PAD];
__device__ __nv_bfloat16  g_B[(size_t)N_BASAL * K_PAD];
__device__ float          g_Bt[(size_t)N_BASAL * K_DIM];
__device__ float          g_sigma[M_ROWS];
__device__ int            g_ccnt[M_ROWS];
__device__ unsigned int   g_cand[(size_t)M_ROWS * MAXC_G];   // 16 MB

// ---------------- asm helpers ----------------
__device__ __forceinline__ uint32_t smem_u32(const void* p) {
    uint32_t a;
    asm("{ .reg .u64 t; cvta.to.shared.u64 t, %1; cvt.u32.u64 %0, t; }" : "=r"(a) : "l"(p));
    return a;
}
__device__ __forceinline__ void cp_async16(uint32_t dst, const void* src) {
    asm volatile("cp.async.cg.shared.global [%0], [%1], 16;" :: "r"(dst), "l"(src) : "memory");
}
__device__ __forceinline__ void cp_commit() {
    asm volatile("cp.async.commit_group;" ::: "memory");
}
template <int N>
__device__ __forceinline__ void cp_wait() {
    asm volatile("cp.async.wait_group %0;" :: "n"(N) : "memory");
}
__device__ __forceinline__ void ldm_x4(uint32_t* r, uint32_t addr) {
    asm volatile("ldmatrix.sync.aligned.m8n8.x4.shared.b16 {%0,%1,%2,%3}, [%4];"
                 : "=r"(r[0]), "=r"(r[1]), "=r"(r[2]), "=r"(r[3]) : "r"(addr));
}
__device__ __forceinline__ void mma_bf16(float* c, const uint32_t* a, uint32_t b0, uint32_t b1) {
    asm volatile("mma.sync.aligned.m16n8k16.row.col.f32.bf16.bf16.f32 "
                 "{%0,%1,%2,%3}, {%4,%5,%6,%7}, {%8,%9}, {%0,%1,%2,%3};"
                 : "+f"(c[0]), "+f"(c[1]), "+f"(c[2]), "+f"(c[3])
                 : "r"(a[0]), "r"(a[1]), "r"(a[2]), "r"(a[3]), "r"(b0), "r"(b1));
}

// ---------------------------------------------------------------------------
// pack synapses into bitmasks + zero per-row counters (fused init)
// ---------------------------------------------------------------------------
__global__ void pack_syn_kernel(const float* __restrict__ syn) {
    int j = blockIdx.x * blockDim.x + threadIdx.x;
    if (j < N_BASAL) {
        unsigned int m = 0;
#pragma unroll
        for (int c = 0; c < NUM_CLS; ++c)
            m |= (syn[c * N_BASAL + j] > 0.5f) ? (1u << c) : 0u;
        g_mask[j] = m;
    }
    if (j < M_ROWS) g_ccnt[j] = 0;
}

// ---------------------------------------------------------------------------
// A: bf16(image) + per-row sigma = 0.1*||x||
// ---------------------------------------------------------------------------
__global__ __launch_bounds__(256)
void conv_a_kernel(const float* __restrict__ img) {
    __shared__ float wsum[8];
    const int m = blockIdx.x;
    const int tid = threadIdx.x;
    const float* src = img + (size_t)m * K_DIM;
    __nv_bfloat16* dst = g_A + (size_t)m * K_PAD;
    float ss = 0.0f;
    for (int k = tid; k < K_PAD; k += 256) {
        float v = (k < K_DIM) ? src[k] : 0.0f;
        dst[k] = __float2bfloat16(v);
        ss = fmaf(v, v, ss);
    }
#pragma unroll
    for (int o = 16; o > 0; o >>= 1) ss += __shfl_xor_sync(0xFFFFFFFFu, ss, o);
    if ((tid & 31) == 0) wsum[tid >> 5] = ss;
    __syncthreads();
    if (tid == 0) {
        float t = 0.0f;
#pragma unroll
        for (int w = 0; w < 8; ++w) t += wsum[w];
        g_sigma[m] = 0.1f * sqrtf(t);
    }
}

// ---------------------------------------------------------------------------
// B: transpose proj -> bf16 g_B [n][K_PAD] and fp32 g_Bt [n][K_DIM]
// ---------------------------------------------------------------------------
__global__ void conv_b_kernel(const float* __restrict__ proj) {
    __shared__ float t[32][33];
    int k0 = blockIdx.x * 32, n0 = blockIdx.y * 32;
    int tx = threadIdx.x, ty = threadIdx.y;   // 32 x 8
#pragma unroll
    for (int i = 0; i < 32; i += 8) {
        int kk = k0 + ty + i;
        t[ty + i][tx] = (kk < K_DIM) ? proj[(size_t)kk * N_BASAL + n0 + tx] : 0.0f;
    }
    __syncthreads();
#pragma unroll
    for (int i = 0; i < 32; i += 8) {
        int n = n0 + ty + i;
        int k = k0 + tx;
        if (k < K_PAD) {
            float v = t[tx][ty + i];
            g_B[(size_t)n * K_PAD + k] = __float2bfloat16(v);
            if (k < K_DIM) g_Bt[(size_t)n * K_DIM + k] = v;
        }
    }
}

// ---------------------------------------------------------------------------
// GEMM (round-13 exact): BK=32, NSTAGE=4, smem-staged emit epilogue
// ---------------------------------------------------------------------------
__global__ __launch_bounds__(256, 2)
void gemm_mma_kernel() {
    extern __shared__ char smem[];
    const uint32_t sb = smem_u32(smem);
    const int tid = threadIdx.x;
    const int lane = tid & 31;
    const int wid = tid >> 5;
    const int warpM = wid >> 2;
    const int warpN = wid & 3;
    const int m0 = blockIdx.y * BM;
    const int n0 = blockIdx.x * BN;

    const char* Abase = (const char*)g_A + (size_t)m0 * (K_PAD * 2);
    const char* Bbase = (const char*)g_B + (size_t)n0 * (K_PAD * 2);

    const int ar = tid >> 2;
    const int ac = tid & 3;

    auto load_stage = [&](int c, int s) {
        const uint32_t st = sb + s * STAGE_BYTES;
        const size_t koff = (size_t)c * (BK * 2);
        cp_async16(st + ar * ROW_BYTES + ac * 16,
                   Abase + (size_t)ar * (K_PAD * 2) + koff + ac * 16);
        cp_async16(st + (ar + 64) * ROW_BYTES + ac * 16,
                   Abase + (size_t)(ar + 64) * (K_PAD * 2) + koff + ac * 16);
        const uint32_t stB = st + A_STAGE_BYTES;
        cp_async16(stB + ar * ROW_BYTES + ac * 16,
                   Bbase + (size_t)ar * (K_PAD * 2) + koff + ac * 16);
        cp_async16(stB + (ar + 64) * ROW_BYTES + ac * 16,
                   Bbase + (size_t)(ar + 64) * (K_PAD * 2) + koff + ac * 16);
        cp_commit();
    };

    float acc[4][4][4];
#pragma unroll
    for (int i = 0; i < 4; ++i)
#pragma unroll
        for (int j = 0; j < 4; ++j)
#pragma unroll
            for (int q = 0; q < 4; ++q) acc[i][j][q] = 0.0f;

    const int lrow = lane & 15;
    const int lcol16 = (lane >> 4) << 4;

    load_stage(0, 0);
    load_stage(1, 1);
    load_stage(2, 2);

    for (int c = 0; c < NCHUNK; ++c) {
        const int s = c & 3;
        cp_wait<2>();
        __syncthreads();
        if (c + 3 < NCHUNK) load_stage(c + 3, (c + 3) & 3);
        else cp_commit();

        const uint32_t stA = sb + s * STAGE_BYTES;
        const uint32_t stB = stA + A_STAGE_BYTES;
#pragma unroll
        for (int ks = 0; ks < 2; ++ks) {
            const int kbyte = ks * 32 + lcol16;
            uint32_t af[4][4];
#pragma unroll
            for (int mt = 0; mt < 4; ++mt)
                ldm_x4(af[mt], stA + (warpM * 64 + mt * 16 + lrow) * ROW_BYTES + kbyte);
            uint32_t bf[2][4];
#pragma unroll
            for (int nt = 0; nt < 2; ++nt)
                ldm_x4(bf[nt], stB + (warpN * 32 + nt * 16 + lrow) * ROW_BYTES + kbyte);
#pragma unroll
            for (int mt = 0; mt < 4; ++mt) {
#pragma unroll
                for (int n8 = 0; n8 < 4; ++n8) {
                    const int nt = n8 >> 1, hi = n8 & 1;
                    mma_bf16(acc[mt][n8], af[mt], bf[nt][hi], bf[nt][hi + 2]);
                }
            }
        }
    }

    // -------- smem-staged emit epilogue --------
    __syncthreads();
    float*        s_lo   = (float*)smem;                      // 512 B
    int*          s_scnt = (int*)(smem + 512);                // 512 B
    unsigned int* s_buf  = (unsigned int*)(smem + 1024);      // 20 KB

    if (tid < BM) {
        const float sg = g_sigma[m0 + tid];
        s_lo[tid] = ZK * sg - (WSIG * sg + AERR) - EMIT_SLACK;
        s_scnt[tid] = 0;
    }
    __syncthreads();

    const int grp = lane >> 2;
    const int tj  = lane & 3;
    float lo8[4][2];
#pragma unroll
    for (int mt = 0; mt < 4; ++mt)
#pragma unroll
        for (int h = 0; h < 2; ++h)
            lo8[mt][h] = s_lo[warpM * 64 + mt * 16 + grp + h * 8];

#pragma unroll
    for (int mt = 0; mt < 4; ++mt) {
#pragma unroll
        for (int n8 = 0; n8 < 4; ++n8) {
#pragma unroll
            for (int q = 0; q < 4; ++q) {
                const int h = q >> 1;
                const float v = acc[mt][n8][q];
                if (v >= lo8[mt][h]) {
                    const int lr = warpM * 64 + mt * 16 + grp + h * 8;
                    const int col = n0 + warpN * 32 + n8 * 8 + tj * 2 + (q & 1);
                    unsigned int pk =
                        ((unsigned int)__half_as_ushort(__float2half_rn(v)) << 16) |
                        (unsigned int)col;
                    int p = atomicAdd(&s_scnt[lr], 1);
                    if (p < ESLOTS) {
                        s_buf[lr * ESLOTS + p] = pk;
                    } else {
                        const int row = m0 + lr;
                        int qg = atomicAdd(&g_ccnt[row], 1);
                        if (qg < MAXC_G) g_cand[(size_t)row * MAXC_G + qg] = pk;
                    }
                }
            }
        }
    }
    __syncthreads();

    if (tid < BM) {
        int c = s_scnt[tid];
        if (c > ESLOTS) c = ESLOTS;
        if (c > 0) {
            const int row = m0 + tid;
            int base = atomicAdd(&g_ccnt[row], c);
            unsigned int* dst = g_cand + (size_t)row * MAXC_G;
            for (int i = 0; i < c; ++i) {
                int p = base + i;
                if (p < MAXC_G) dst[p] = s_buf[tid * ESLOTS + i];
            }
        }
    }
}

// ---------------------------------------------------------------------------
// finalize (one block / row)
// ---------------------------------------------------------------------------
__global__ __launch_bounds__(256)
void finalize_kernel(const float* __restrict__ img, float* __restrict__ out) {
    const int row = blockIdx.x;
    const int tid = threadIdx.x;
    const int lane = tid & 31;
    const int wid = tid >> 5;

    __shared__ float cval[MAXC_G];
    __shared__ int   ccol[MAXC_G];
    __shared__ float4 s_img[K_DIM / 4];
    __shared__ unsigned int hist[PBINS];
    __shared__ int s_nsure, s_pb, s_nband, s_ntop;
    __shared__ int bidx[MAXBAND];
    __shared__ float bval[MAXBAND];
    __shared__ int ov[NUM_CLS];

    const int C = min(g_ccnt[row], MAXC_G);
    const float sig = g_sigma[row];
    const float tau = ZK * sig;
    const float w = WSIG * sig + AERR;
    const float lo = tau - w;
    const float hi = tau + w;
    const float binw = (hi - lo) / (float)PBINS;
    const float invbw = 1.0f / binw;

    const float4* img4 = (const float4*)(img + (size_t)row * K_DIM);
    for (int k = tid; k < K_DIM / 4; k += 256) s_img[k] = img4[k];
    for (int i = tid; i < PBINS; i += 256) hist[i] = 0;
    if (tid == 0) { s_nsure = 0; s_pb = -1; s_nband = 0; s_ntop = 0; }
    if (tid < NUM_CLS) ov[tid] = 0;

    const unsigned int* cp = g_cand + (size_t)row * MAXC_G;
    for (int i = tid; i < C; i += 256) {
        unsigned int p = cp[i];
        cval[i] = __half2float(__ushort_as_half((unsigned short)(p >> 16)));
        ccol[i] = (int)(p & 0xFFFFu);
    }
    __syncthreads();

    int cnt[NUM_CLS];
#pragma unroll
    for (int c = 0; c < NUM_CLS; ++c) cnt[c] = 0;

    int nsure = 0;
    for (int i = tid; i < C; i += 256) {
        const float v = cval[i];
        if (v > hi) {
            unsigned int m = g_mask[ccol[i]];
#pragma unroll
            for (int c = 0; c < NUM_CLS; ++c) cnt[c] += (m >> c) & 1u;
            ++nsure;
        } else {
            int b = (int)((v - lo) * invbw);
            b = min(max(b, 0), PBINS - 1);
            atomicAdd(&hist[b], 1u);
        }
    }
    atomicAdd(&s_nsure, nsure);
    __syncthreads();

    int k_remain = NUM_ACT - s_nsure;
    const int C_win = C - s_nsure;

    if (k_remain > 0 && k_remain >= C_win) {
        for (int i = tid; i < C; i += 256) {
            if (cval[i] <= hi) {
                unsigned int m = g_mask[ccol[i]];
#pragma unroll
                for (int c = 0; c < NUM_CLS; ++c) cnt[c] += (m >> c) & 1u;
            }
        }
    } else if (k_remain > 0) {
        if (wid == 0) {
            const unsigned int kk = (unsigned int)k_remain;
            unsigned int sum = 0;
            for (int i = 0; i < PBINS / 32; ++i)
                sum += hist[PBINS - 1 - lane * (PBINS / 32) - i];
            unsigned int pre = sum;
#pragma unroll
            for (int o = 1; o < 32; o <<= 1) {
                unsigned int t = __shfl_up_sync(0xFFFFFFFFu, pre, o);
                if (lane >= o) pre += t;
            }
            const unsigned int excl = pre - sum;
            if (excl < kk && pre >= kk) {
                unsigned int before = excl;
                for (int i = 0; i < PBINS / 32; ++i) {
                    int b = PBINS - 1 - lane * (PBINS / 32) - i;
                    unsigned int cc = hist[b];
                    if (before + cc >= kk) { s_pb = b; break; }
                    before += cc;
                }
            }
        }
        __syncthreads();

        const int pb = (s_pb >= 0) ? s_pb : 0;
        const float hi2 = lo + (float)(pb + 1) * binw + BW;
        const float lo2 = lo + (float)pb * binw - BW;

        int ntop = 0;
        for (int i = tid; i < C; i += 256) {
            const float v = cval[i];
            if (v > hi) continue;
            if (v > hi2) {
                unsigned int m = g_mask[ccol[i]];
#pragma unroll
                for (int c = 0; c < NUM_CLS; ++c) cnt[c] += (m >> c) & 1u;
                ++ntop;
            } else if (v >= lo2) {
                int p = atomicAdd(&s_nband, 1);
                if (p < MAXBAND) bidx[p] = ccol[i];
            }
        }
        atomicAdd(&s_ntop, ntop);
        __syncthreads();

        const int nband = min(s_nband, MAXBAND);
        for (int b = wid; b < nband; b += 8) {
            const float4* brow = (const float4*)(g_Bt + (size_t)bidx[b] * K_DIM);
            float s = 0.0f;
            for (int k = lane; k < K_DIM / 4; k += 32) {
                float4 bb = brow[k];
                float4 im = s_img[k];
                s = fmaf(im.x, bb.x, s);
                s = fmaf(im.y, bb.y, s);
                s = fmaf(im.z, bb.z, s);
                s = fmaf(im.w, bb.w, s);
            }
#pragma unroll
            for (int o = 16; o > 0; o >>= 1)
                s += __shfl_xor_sync(0xFFFFFFFFu, s, o);
            if (lane == 0) bval[b] = s;
        }
        __syncthreads();

        const int slots = k_remain - s_ntop;
        for (int b = tid; b < nband; b += 256) {
            const float vb = bval[b];
            const int ib = bidx[b];
            int r = 0;
            for (int d = 0; d < nband; ++d) {
                float vd = bval[d];
                r += (vd > vb || (vd == vb && bidx[d] < ib)) ? 1 : 0;
            }
            if (r < slots) {
                unsigned int m = g_mask[ib];
#pragma unroll
                for (int c = 0; c < NUM_CLS; ++c) cnt[c] += (m >> c) & 1u;
            }
        }
    }

#pragma unroll
    for (int c = 0; c < NUM_CLS; ++c)
        if (cnt[c]) atomicAdd(&ov[c], cnt[c]);
    __syncthreads();

    if (tid < NUM_CLS)
        out[row * NUM_CLS + tid] = (float)ov[tid];
}

// ---------------------------------------------------------------------------
// Launch
// ---------------------------------------------------------------------------
extern "C" void kernel_launch(void* const* d_in, const int* in_sizes, int n_in,
                              void* d_out, int out_size) {
    const float* image = (const float*)d_in[0];
    const float* proj  = (const float*)d_in[1];
    const float* syn   = (const float*)d_in[2];
    float* out = (float*)d_out;

    cudaFuncSetAttribute(gemm_mma_kernel, cudaFuncAttributeMaxDynamicSharedMemorySize, SMEM_TOTAL);

    pack_syn_kernel<<<(N_BASAL + 255) / 256, 256>>>(syn);
    conv_a_kernel<<<M_ROWS, 256>>>(image);
    {
        dim3 grid(K_PAD / 32, N_BASAL / 32);      // 25 x 512
        conv_b_kernel<<<grid, dim3(32, 8)>>>(proj);
    }
    {
        dim3 grid(N_BASAL / BN, M_ROWS / BM);     // 128 x 32
        gemm_mma_kernel<<<grid, 256, SMEM_TOTAL>>>();
    }
    finalize_kernel<<<M_ROWS, 256>>>(image, out);
}

// round 16
// speedup vs baseline: 1.0327x; 1.0084x over previous
#include <cuda_runtime.h>
#include <cuda_bf16.h>
#include <cuda_fp16.h>
#include <cstdint>

// ---------------- problem constants ----------------
#define M_ROWS   4096
#define K_DIM    784
#define K_PAD    800           // 784 padded to 25*32
#define N_BASAL  16384
#define NUM_CLS  10
#define NUM_ACT  492
#define ZK       1.8806f       // Phi^-1(1 - 492/16384)
#define WSIG     0.10f         // window half-width in sigma units (5.1 SE)
#define AERR     0.035f        // bf16 GEMM err (0.03) + fp16 pack err (0.005)
#define BW       0.08f         // rescore band half-width
#define EMIT_SLACK 0.01f
#define MAXC_G   1024
#define MAXBAND  256
#define PBINS    256
#define ESLOTS   40

// ---------------- GEMM tiling: 128x128 CTA, 16 warps (32x32 warp tile) ----
#define BM 128
#define BN 128
#define BK 32
#define NCHUNK (K_PAD / BK)    // 25
#define NSTAGE 4
#define ROW_BYTES 80
#define A_STAGE_BYTES (BM * ROW_BYTES)
#define B_STAGE_BYTES (BN * ROW_BYTES)
#define STAGE_BYTES (A_STAGE_BYTES + B_STAGE_BYTES)
#define SMEM_TOTAL (NSTAGE * STAGE_BYTES)   // 81920 -> 2 CTAs/SM
#define GTHREADS 512

// ---------------- scratch ----------------
__device__ unsigned int   g_mask[N_BASAL];
__device__ __nv_bfloat16  g_A[(size_t)M_ROWS * K_PAD];
__device__ __nv_bfloat16  g_B[(size_t)N_BASAL * K_PAD];
__device__ float          g_Bt[(size_t)N_BASAL * K_DIM];
__device__ float          g_sigma[M_ROWS];
__device__ int            g_ccnt[M_ROWS];
__device__ unsigned int   g_cand[(size_t)M_ROWS * MAXC_G];   // 16 MB

// ---------------- asm helpers ----------------
__device__ __forceinline__ uint32_t smem_u32(const void* p) {
    uint32_t a;
    asm("{ .reg .u64 t; cvta.to.shared.u64 t, %1; cvt.u32.u64 %0, t; }" : "=r"(a) : "l"(p));
    return a;
}
__device__ __forceinline__ void cp_async16(uint32_t dst, const void* src) {
    asm volatile("cp.async.cg.shared.global [%0], [%1], 16;" :: "r"(dst), "l"(src) : "memory");
}
__device__ __forceinline__ void cp_commit() {
    asm volatile("cp.async.commit_group;" ::: "memory");
}
template <int N>
__device__ __forceinline__ void cp_wait() {
    asm volatile("cp.async.wait_group %0;" :: "n"(N) : "memory");
}
__device__ __forceinline__ void ldm_x4(uint32_t* r, uint32_t addr) {
    asm volatile("ldmatrix.sync.aligned.m8n8.x4.shared.b16 {%0,%1,%2,%3}, [%4];"
                 : "=r"(r[0]), "=r"(r[1]), "=r"(r[2]), "=r"(r[3]) : "r"(addr));
}
__device__ __forceinline__ void mma_bf16(float* c, const uint32_t* a, uint32_t b0, uint32_t b1) {
    asm volatile("mma.sync.aligned.m16n8k16.row.col.f32.bf16.bf16.f32 "
                 "{%0,%1,%2,%3}, {%4,%5,%6,%7}, {%8,%9}, {%0,%1,%2,%3};"
                 : "+f"(c[0]), "+f"(c[1]), "+f"(c[2]), "+f"(c[3])
                 : "r"(a[0]), "r"(a[1]), "r"(a[2]), "r"(a[3]), "r"(b0), "r"(b1));
}

// ---------------------------------------------------------------------------
// pack synapses into bitmasks + zero per-row counters (fused init)
// ---------------------------------------------------------------------------
__global__ void pack_syn_kernel(const float* __restrict__ syn) {
    int j = blockIdx.x * blockDim.x + threadIdx.x;
    if (j < N_BASAL) {
        unsigned int m = 0;
#pragma unroll
        for (int c = 0; c < NUM_CLS; ++c)
            m |= (syn[c * N_BASAL + j] > 0.5f) ? (1u << c) : 0u;
        g_mask[j] = m;
    }
    if (j < M_ROWS) g_ccnt[j] = 0;
}

// ---------------------------------------------------------------------------
// A: bf16(image) + per-row sigma = 0.1*||x||
// ---------------------------------------------------------------------------
__global__ __launch_bounds__(256)
void conv_a_kernel(const float* __restrict__ img) {
    __shared__ float wsum[8];
    const int m = blockIdx.x;
    const int tid = threadIdx.x;
    const float* src = img + (size_t)m * K_DIM;
    __nv_bfloat16* dst = g_A + (size_t)m * K_PAD;
    float ss = 0.0f;
    for (int k = tid; k < K_PAD; k += 256) {
        float v = (k < K_DIM) ? src[k] : 0.0f;
        dst[k] = __float2bfloat16(v);
        ss = fmaf(v, v, ss);
    }
#pragma unroll
    for (int o = 16; o > 0; o >>= 1) ss += __shfl_xor_sync(0xFFFFFFFFu, ss, o);
    if ((tid & 31) == 0) wsum[tid >> 5] = ss;
    __syncthreads();
    if (tid == 0) {
        float t = 0.0f;
#pragma unroll
        for (int w = 0; w < 8; ++w) t += wsum[w];
        g_sigma[m] = 0.1f * sqrtf(t);
    }
}

// ---------------------------------------------------------------------------
// B: transpose proj -> bf16 g_B [n][K_PAD] and fp32 g_Bt [n][K_DIM]
// ---------------------------------------------------------------------------
__global__ void conv_b_kernel(const float* __restrict__ proj) {
    __shared__ float t[32][33];
    int k0 = blockIdx.x * 32, n0 = blockIdx.y * 32;
    int tx = threadIdx.x, ty = threadIdx.y;   // 32 x 8
#pragma unroll
    for (int i = 0; i < 32; i += 8) {
        int kk = k0 + ty + i;
        t[ty + i][tx] = (kk < K_DIM) ? proj[(size_t)kk * N_BASAL + n0 + tx] : 0.0f;
    }
    __syncthreads();
#pragma unroll
    for (int i = 0; i < 32; i += 8) {
        int n = n0 + ty + i;
        int k = k0 + tx;
        if (k < K_PAD) {
            float v = t[tx][ty + i];
            g_B[(size_t)n * K_PAD + k] = __float2bfloat16(v);
            if (k < K_DIM) g_Bt[(size_t)n * K_DIM + k] = v;
        }
    }
}

// ---------------------------------------------------------------------------
// GEMM: 128x128 CTA, 512 threads, 16 warps of 32x32 tile, BK=32, NSTAGE=4,
// smem-staged emit epilogue. 2 CTAs/SM = 32 warps/SM.
// ---------------------------------------------------------------------------
__global__ __launch_bounds__(GTHREADS, 2)
void gemm_mma_kernel() {
    extern __shared__ char smem[];
    const uint32_t sb = smem_u32(smem);
    const int tid = threadIdx.x;
    const int lane = tid & 31;
    const int wid = tid >> 5;            // 0..15
    const int warpM = wid >> 2;          // 0..3
    const int warpN = wid & 3;           // 0..3
    const int m0 = blockIdx.y * BM;
    const int n0 = blockIdx.x * BN;

    const char* Abase = (const char*)g_A + (size_t)m0 * (K_PAD * 2);
    const char* Bbase = (const char*)g_B + (size_t)n0 * (K_PAD * 2);

    // loader: 512 threads cover A(512) + B(512) 16B chunks, 2 each
    const int lr = tid >> 2;             // row 0..127
    const int ac = tid & 3;              // chunk in 64B row

    auto load_stage = [&](int c, int s) {
        const uint32_t st = sb + s * STAGE_BYTES;
        const size_t koff = (size_t)c * (BK * 2);
        cp_async16(st + lr * ROW_BYTES + ac * 16,
                   Abase + (size_t)lr * (K_PAD * 2) + koff + ac * 16);
        cp_async16(st + A_STAGE_BYTES + lr * ROW_BYTES + ac * 16,
                   Bbase + (size_t)lr * (K_PAD * 2) + koff + ac * 16);
        cp_commit();
    };

    float acc[2][4][4];
#pragma unroll
    for (int i = 0; i < 2; ++i)
#pragma unroll
        for (int j = 0; j < 4; ++j)
#pragma unroll
            for (int q = 0; q < 4; ++q) acc[i][j][q] = 0.0f;

    const int lrow = lane & 15;
    const int lcol16 = (lane >> 4) << 4;

    load_stage(0, 0);
    load_stage(1, 1);
    load_stage(2, 2);

    for (int c = 0; c < NCHUNK; ++c) {
        const int s = c & 3;
        cp_wait<2>();
        __syncthreads();
        if (c + 3 < NCHUNK) load_stage(c + 3, (c + 3) & 3);
        else cp_commit();

        const uint32_t stA = sb + s * STAGE_BYTES;
        const uint32_t stB = stA + A_STAGE_BYTES;
#pragma unroll
        for (int ks = 0; ks < 2; ++ks) {
            const int kbyte = ks * 32 + lcol16;
            uint32_t af[2][4];
#pragma unroll
            for (int mt = 0; mt < 2; ++mt)
                ldm_x4(af[mt], stA + (warpM * 32 + mt * 16 + lrow) * ROW_BYTES + kbyte);
            uint32_t bf[2][4];
#pragma unroll
            for (int nt = 0; nt < 2; ++nt)
                ldm_x4(bf[nt], stB + (warpN * 32 + nt * 16 + lrow) * ROW_BYTES + kbyte);
#pragma unroll
            for (int mt = 0; mt < 2; ++mt) {
#pragma unroll
                for (int n8 = 0; n8 < 4; ++n8) {
                    const int nt = n8 >> 1, hi = n8 & 1;
                    mma_bf16(acc[mt][n8], af[mt], bf[nt][hi], bf[nt][hi + 2]);
                }
            }
        }
    }

    // -------- smem-staged emit epilogue --------
    __syncthreads();
    float*        s_lo   = (float*)smem;                      // 512 B
    int*          s_scnt = (int*)(smem + 512);                // 512 B
    unsigned int* s_buf  = (unsigned int*)(smem + 1024);      // 20 KB

    if (tid < BM) {
        const float sg = g_sigma[m0 + tid];
        s_lo[tid] = ZK * sg - (WSIG * sg + AERR) - EMIT_SLACK;
        s_scnt[tid] = 0;
    }
    __syncthreads();

    const int grp = lane >> 2;
    const int tj  = lane & 3;
    float lo8[2][2];
#pragma unroll
    for (int mt = 0; mt < 2; ++mt)
#pragma unroll
        for (int h = 0; h < 2; ++h)
            lo8[mt][h] = s_lo[warpM * 32 + mt * 16 + grp + h * 8];

#pragma unroll
    for (int mt = 0; mt < 2; ++mt) {
#pragma unroll
        for (int n8 = 0; n8 < 4; ++n8) {
#pragma unroll
            for (int q = 0; q < 4; ++q) {
                const int h = q >> 1;
                const float v = acc[mt][n8][q];
                if (v >= lo8[mt][h]) {
                    const int lr2 = warpM * 32 + mt * 16 + grp + h * 8;
                    const int col = n0 + warpN * 32 + n8 * 8 + tj * 2 + (q & 1);
                    unsigned int pk =
                        ((unsigned int)__half_as_ushort(__float2half_rn(v)) << 16) |
                        (unsigned int)col;
                    int p = atomicAdd(&s_scnt[lr2], 1);
                    if (p < ESLOTS) {
                        s_buf[lr2 * ESLOTS + p] = pk;
                    } else {
                        const int row = m0 + lr2;
                        int qg = atomicAdd(&g_ccnt[row], 1);
                        if (qg < MAXC_G) g_cand[(size_t)row * MAXC_G + qg] = pk;
                    }
                }
            }
        }
    }
    __syncthreads();

    if (tid < BM) {
        int c = s_scnt[tid];
        if (c > ESLOTS) c = ESLOTS;
        if (c > 0) {
            const int row = m0 + tid;
            int base = atomicAdd(&g_ccnt[row], c);
            unsigned int* dst = g_cand + (size_t)row * MAXC_G;
            for (int i = 0; i < c; ++i) {
                int p = base + i;
                if (p < MAXC_G) dst[p] = s_buf[tid * ESLOTS + i];
            }
        }
    }
}

// ---------------------------------------------------------------------------
// finalize (one block / row)
// ---------------------------------------------------------------------------
__global__ __launch_bounds__(256)
void finalize_kernel(const float* __restrict__ img, float* __restrict__ out) {
    const int row = blockIdx.x;
    const int tid = threadIdx.x;
    const int lane = tid & 31;
    const int wid = tid >> 5;

    __shared__ float cval[MAXC_G];
    __shared__ int   ccol[MAXC_G];
    __shared__ float4 s_img[K_DIM / 4];
    __shared__ unsigned int hist[PBINS];
    __shared__ int s_nsure, s_pb, s_nband, s_ntop;
    __shared__ int bidx[MAXBAND];
    __shared__ float bval[MAXBAND];
    __shared__ int ov[NUM_CLS];

    const int C = min(g_ccnt[row], MAXC_G);
    const float sig = g_sigma[row];
    const float tau = ZK * sig;
    const float w = WSIG * sig + AERR;
    const float lo = tau - w;
    const float hi = tau + w;
    const float binw = (hi - lo) / (float)PBINS;
    const float invbw = 1.0f / binw;

    const float4* img4 = (const float4*)(img + (size_t)row * K_DIM);
    for (int k = tid; k < K_DIM / 4; k += 256) s_img[k] = img4[k];
    for (int i = tid; i < PBINS; i += 256) hist[i] = 0;
    if (tid == 0) { s_nsure = 0; s_pb = -1; s_nband = 0; s_ntop = 0; }
    if (tid < NUM_CLS) ov[tid] = 0;

    const unsigned int* cp = g_cand + (size_t)row * MAXC_G;
    for (int i = tid; i < C; i += 256) {
        unsigned int p = cp[i];
        cval[i] = __half2float(__ushort_as_half((unsigned short)(p >> 16)));
        ccol[i] = (int)(p & 0xFFFFu);
    }
    __syncthreads();

    int cnt[NUM_CLS];
#pragma unroll
    for (int c = 0; c < NUM_CLS; ++c) cnt[c] = 0;

    int nsure = 0;
    for (int i = tid; i < C; i += 256) {
        const float v = cval[i];
        if (v > hi) {
            unsigned int m = g_mask[ccol[i]];
#pragma unroll
            for (int c = 0; c < NUM_CLS; ++c) cnt[c] += (m >> c) & 1u;
            ++nsure;
        } else {
            int b = (int)((v - lo) * invbw);
            b = min(max(b, 0), PBINS - 1);
            atomicAdd(&hist[b], 1u);
        }
    }
    atomicAdd(&s_nsure, nsure);
    __syncthreads();

    int k_remain = NUM_ACT - s_nsure;
    const int C_win = C - s_nsure;

    if (k_remain > 0 && k_remain >= C_win) {
        for (int i = tid; i < C; i += 256) {
            if (cval[i] <= hi) {
                unsigned int m = g_mask[ccol[i]];
#pragma unroll
                for (int c = 0; c < NUM_CLS; ++c) cnt[c] += (m >> c) & 1u;
            }
        }
    } else if (k_remain > 0) {
        if (wid == 0) {
            const unsigned int kk = (unsigned int)k_remain;
            unsigned int sum = 0;
            for (int i = 0; i < PBINS / 32; ++i)
                sum += hist[PBINS - 1 - lane * (PBINS / 32) - i];
            unsigned int pre = sum;
#pragma unroll
            for (int o = 1; o < 32; o <<= 1) {
                unsigned int t = __shfl_up_sync(0xFFFFFFFFu, pre, o);
                if (lane >= o) pre += t;
            }
            const unsigned int excl = pre - sum;
            if (excl < kk && pre >= kk) {
                unsigned int before = excl;
                for (int i = 0; i < PBINS / 32; ++i) {
                    int b = PBINS - 1 - lane * (PBINS / 32) - i;
                    unsigned int cc = hist[b];
                    if (before + cc >= kk) { s_pb = b; break; }
                    before += cc;
                }
            }
        }
        __syncthreads();

        const int pb = (s_pb >= 0) ? s_pb : 0;
        const float hi2 = lo + (float)(pb + 1) * binw + BW;
        const float lo2 = lo + (float)pb * binw - BW;

        int ntop = 0;
        for (int i = tid; i < C; i += 256) {
            const float v = cval[i];
            if (v > hi) continue;
            if (v > hi2) {
                unsigned int m = g_mask[ccol[i]];
#pragma unroll
                for (int c = 0; c < NUM_CLS; ++c) cnt[c] += (m >> c) & 1u;
                ++ntop;
            } else if (v >= lo2) {
                int p = atomicAdd(&s_nband, 1);
                if (p < MAXBAND) bidx[p] = ccol[i];
            }
        }
        atomicAdd(&s_ntop, ntop);
        __syncthreads();

        const int nband = min(s_nband, MAXBAND);
        for (int b = wid; b < nband; b += 8) {
            const float4* brow = (const float4*)(g_Bt + (size_t)bidx[b] * K_DIM);
            float s = 0.0f;
            for (int k = lane; k < K_DIM / 4; k += 32) {
                float4 bb = brow[k];
                float4 im = s_img[k];
                s = fmaf(im.x, bb.x, s);
                s = fmaf(im.y, bb.y, s);
                s = fmaf(im.z, bb.z, s);
                s = fmaf(im.w, bb.w, s);
            }
#pragma unroll
            for (int o = 16; o > 0; o >>= 1)
                s += __shfl_xor_sync(0xFFFFFFFFu, s, o);
            if (lane == 0) bval[b] = s;
        }
        __syncthreads();

        const int slots = k_remain - s_ntop;
        for (int b = tid; b < nband; b += 256) {
            const float vb = bval[b];
            const int ib = bidx[b];
            int r = 0;
            for (int d = 0; d < nband; ++d) {
                float vd = bval[d];
                r += (vd > vb || (vd == vb && bidx[d] < ib)) ? 1 : 0;
            }
            if (r < slots) {
                unsigned int m = g_mask[ib];
#pragma unroll
                for (int c = 0; c < NUM_CLS; ++c) cnt[c] += (m >> c) & 1u;
            }
        }
    }

#pragma unroll
    for (int c = 0; c < NUM_CLS; ++c)
        if (cnt[c]) atomicAdd(&ov[c], cnt[c]);
    __syncthreads();

    if (tid < NUM_CLS)
        out[row * NUM_CLS + tid] = (float)ov[tid];
}

// ---------------------------------------------------------------------------
// Launch
// ---------------------------------------------------------------------------
extern "C" void kernel_launch(void* const* d_in, const int* in_sizes, int n_in,
                              void* d_out, int out_size) {
    const float* image = (const float*)d_in[0];
    const float* proj  = (const float*)d_in[1];
    const float* syn   = (const float*)d_in[2];
    float* out = (float*)d_out;

    cudaFuncSetAttribute(gemm_mma_kernel, cudaFuncAttributeMaxDynamicSharedMemorySize, SMEM_TOTAL);

    pack_syn_kernel<<<(N_BASAL + 255) / 256, 256>>>(syn);
    conv_a_kernel<<<M_ROWS, 256>>>(image);
    {
        dim3 grid(K_PAD / 32, N_BASAL / 32);      // 25 x 512
        conv_b_kernel<<<grid, dim3(32, 8)>>>(proj);
    }
    {
        dim3 grid(N_BASAL / BN, M_ROWS / BM);     // 128 x 32
        gemm_mma_kernel<<<grid, GTHREADS, SMEM_TOTAL>>>();
    }
    finalize_kernel<<<M_ROWS, 256>>>(image, out);
}